// round 15
// baseline (speedup 1.0000x reference)
#include <cuda_runtime.h>
#include <cuda_bf16.h>

#define BB 512
#define TT 512
#define LL 64
#define KSEG 5
#define WBURN 16

__device__ float g_res[BB];
__device__ float g_R[BB * KSEG];
__device__ float g_path[BB];
__device__ unsigned int g_cnt[BB];
__device__ unsigned int g_done = 0;

static __device__ __forceinline__ __nv_bfloat162 asbf2(unsigned int u) {
    return *reinterpret_cast<__nv_bfloat162*>(&u);
}
static __device__ __forceinline__ float bflo(__nv_bfloat162 v) {
    unsigned int u = *reinterpret_cast<unsigned int*>(&v);
    return __uint_as_float(u << 16);
}
static __device__ __forceinline__ float bfhi(__nv_bfloat162 v) {
    unsigned int u = *reinterpret_cast<unsigned int*>(&v);
    return __uint_as_float(u & 0xFFFF0000u);
}

__global__ void __launch_bounds__(32) crf_main_kernel(
    const float* __restrict__ emission,   // [B,T,L]
    const int*   __restrict__ target,     // [B,T]
    const float* __restrict__ mask,       // [B,T]
    const float* __restrict__ start_trans,// [L]
    const float* __restrict__ trans,      // [L,L]
    const float* __restrict__ end_trans,  // [L]
    float* __restrict__ out)
{
    __shared__ __align__(16) unsigned int sm_p[2][32]; // packed bf16x2 V
    __shared__ float sm_v0[2];

    const int lane = threadIdx.x;
    const int b    = blockIdx.x & (BB - 1);
    const int s    = blockIdx.x >> 9;            // segment 0..KSEG-1

    const float*  emb  = emission + (size_t)b * TT * LL;
    const float2* emb2 = (const float2*)emb;     // idx: t*32 + lane
    const float*  mrow = mask + (size_t)b * TT;

    // effective length Lb (binary prefix mask)
    float msum = 0.0f;
    for (int t = lane; t < TT; t += 32) msum += mrow[t];
    #pragma unroll
    for (int o = 16; o; o >>= 1) msum += __shfl_xor_sync(~0u, msum, o);
    const int Lb = (int)(msum + 0.5f);

    const int c0 = (s * (Lb - 1)) / KSEG;        // segment start point
    const int c1 = ((s + 1) * (Lb - 1)) / KSEG;  // segment end point
    int t0 = (s == 0) ? 0 : (c0 - WBURN);
    if (t0 < 0) t0 = 0;

    // E columns 2l, 2l+1, packed over i-pairs
    __nv_bfloat162 EpA[32], EpB[32];
    #pragma unroll
    for (int k = 0; k < 32; k++) {
        const float2 r0 = ((const float2*)trans)[(2 * k)     * 32 + lane];
        const float2 r1 = ((const float2*)trans)[(2 * k + 1) * 32 + lane];
        EpA[k] = __floats2bfloat162_rn(__expf(r0.x), __expf(r1.x));
        EpB[k] = __floats2bfloat162_rn(__expf(r0.y), __expf(r1.y));
    }

    // path score (segment-0 CTA only; exact fp32, general masked form)
    float pacc = 0.0f;
    if (s == 0) {
        const int* tgt = target + (size_t)b * TT;
        for (int t = 1 + lane; t < TT; t += 32) {
            const int   tp = tgt[t - 1];
            const int   tc = tgt[t];
            const float m  = mrow[t];
            const float nm = (t + 1 < TT) ? mrow[t + 1] : 0.0f;
            const float e  = (m > nm) ? 1.0f : 0.0f;
            pacc += m * (trans[tp * LL + tc] + emb[(size_t)t * LL + tc])
                  + e * end_trans[tc];
        }
        if (lane == 0) {
            const int tg0 = tgt[0];
            pacc += start_trans[tg0] + emb[tg0];
        }
        #pragma unroll
        for (int o = 16; o; o >>= 1) pacc += __shfl_xor_sync(~0u, pacc, o);
    }

    // ---- init at t0 ----
    const float2 em_t0 = emb2[(size_t)t0 * 32 + lane];
    float iA, iB;
    if (s == 0) {
        const float2 st2 = ((const float2*)start_trans)[lane];
        iA = st2.x + em_t0.x;
        iB = st2.y + em_t0.y;
    } else {
        iA = em_t0.x;
        iB = em_t0.y;
    }
    const float C0shift = __shfl_sync(~0u, iA, 0);
    float VA = __expf(iA - C0shift);
    float VB = __expf(iB - C0shift);
    {
        const __nv_bfloat162 pv = __floats2bfloat162_rn(VA, VB);
        sm_p[t0 & 1][lane] = *reinterpret_cast<const unsigned int*>(&pv);
        if (lane == 0) sm_v0[t0 & 1] = VA;
    }

    float C = 0.0f, prod = 1.0f, Sstart = 0.0f;
    if (c0 == t0) {                              // s==0 (or degenerate)
        float sum = VA + VB;
        #pragma unroll
        for (int o = 16; o; o >>= 1) sum += __shfl_xor_sync(~0u, sum, o);
        Sstart = __logf(sum);
    }

    // emission pipeline
    int i1 = t0 + 1; if (i1 > TT - 1) i1 = TT - 1;
    int i2 = t0 + 2; if (i2 > TT - 1) i2 = TT - 1;
    float2 em1 = emb2[(size_t)i1 * 32 + lane];
    float2 em2 = emb2[(size_t)i2 * 32 + lane];
    float XcA = __expf(em1.x), XcB = __expf(em1.y);
    __syncwarp();

    for (int t = t0 + 1; t <= c1; t++) {
        const int pb = (t - 1) & 1, cb = t & 1;
        const float u0 = sm_v0[pb];
        float w;
        asm("rcp.approx.f32 %0, %1;" : "=f"(w) : "f"(u0));
        const float XnA = __expf(em2.x);
        const float XnB = __expf(em2.y);
        if (t + 2 < TT) em2 = emb2[(size_t)(t + 2) * 32 + lane];

        // dot over i for both labels: 64 HFMA2
        const uint4* q = (const uint4*)sm_p[pb];
        const __nv_bfloat162 z2 = __float2bfloat162_rn(0.0f);
        __nv_bfloat162 a0 = z2, a1 = z2, a2 = z2, a3 = z2;
        __nv_bfloat162 c0v = z2, c1v = z2, c2v = z2, c3v = z2;
        #pragma unroll
        for (int k = 0; k < 8; k++) {
            const uint4 uu = q[k];
            const __nv_bfloat162 q0 = asbf2(uu.x);
            const __nv_bfloat162 q1 = asbf2(uu.y);
            const __nv_bfloat162 q2 = asbf2(uu.z);
            const __nv_bfloat162 q3 = asbf2(uu.w);
            a0  = __hfma2(q0, EpA[4 * k + 0], a0);
            c0v = __hfma2(q0, EpB[4 * k + 0], c0v);
            a1  = __hfma2(q1, EpA[4 * k + 1], a1);
            c1v = __hfma2(q1, EpB[4 * k + 1], c1v);
            a2  = __hfma2(q2, EpA[4 * k + 2], a2);
            c2v = __hfma2(q2, EpB[4 * k + 2], c2v);
            a3  = __hfma2(q3, EpA[4 * k + 3], a3);
            c3v = __hfma2(q3, EpB[4 * k + 3], c3v);
        }
        const __nv_bfloat162 tA = __hadd2(__hadd2(a0, a1), __hadd2(a2, a3));
        const __nv_bfloat162 tB = __hadd2(__hadd2(c0v, c1v), __hadd2(c2v, c3v));
        const float dotA = bflo(tA) + bfhi(tA);
        const float dotB = bflo(tB) + bfhi(tB);

        VA = dotA * (XcA * w);
        VB = dotB * (XcB * w);
        prod *= u0;
        if ((t & 3) == 0) { C += __logf(prod); prod = 1.0f; }

        if (t == c0) {                           // end of burn-in: reset stats
            C = 0.0f; prod = 1.0f;
            float sum = VA + VB;
            #pragma unroll
            for (int o = 16; o; o >>= 1) sum += __shfl_xor_sync(~0u, sum, o);
            Sstart = __logf(sum);
        }

        const __nv_bfloat162 pv = __floats2bfloat162_rn(VA, VB);
        sm_p[cb][lane] = *reinterpret_cast<const unsigned int*>(&pv);
        if (lane == 0) sm_v0[cb] = VA;
        XcA = XnA; XcB = XnB;
        __syncwarp();
    }
    C += __logf(prod);

    if (s == KSEG - 1) {                         // fold end_trans at t=Lb-1
        const float2 et2 = ((const float2*)end_trans)[lane];
        VA *= __expf(et2.x);
        VB *= __expf(et2.y);
    }
    float sum = VA + VB;
    #pragma unroll
    for (int o = 16; o; o >>= 1) sum += __shfl_xor_sync(~0u, sum, o);
    float Rs = C + __logf(sum) - Sstart;
    if (s == 0) Rs += Sstart + C0shift;          // + log F_0

    // ---------------- per-batch combine, then global mean ----------------
    if (lane == 0) {
        g_R[b * KSEG + s] = Rs;
        if (s == 0) g_path[b] = pacc;
    }
    __threadfence();
    unsigned int tk = 0;
    if (lane == 0) tk = atomicAdd(&g_cnt[b], 1u);
    tk = __shfl_sync(~0u, tk, 0);
    if (tk == KSEG - 1) {                        // last segment for batch b
        __threadfence();
        unsigned int td = 0;
        if (lane == 0) {
            float z = 0.0f;
            #pragma unroll
            for (int k = 0; k < KSEG; k++) z += g_R[b * KSEG + k];
            g_res[b] = z - g_path[b];
            g_cnt[b] = 0;                        // reset for graph replay
            __threadfence();
            td = atomicAdd(&g_done, 1u);         // BB-1 for the last batch
        }
        td = __shfl_sync(~0u, td, 0);
        if (td == BB - 1) {
            __threadfence();                     // acquire all g_res
            float acc = 0.0f;
            #pragma unroll
            for (int k = 0; k < BB / 32; k++) acc += g_res[lane + k * 32];
            #pragma unroll
            for (int o = 16; o; o >>= 1) acc += __shfl_xor_sync(~0u, acc, o);
            if (lane == 0) {
                out[0] = acc * (1.0f / BB);
                g_done = 0;                      // reset for graph replay
            }
        }
    }
}

extern "C" void kernel_launch(void* const* d_in, const int* in_sizes, int n_in,
                              void* d_out, int out_size) {
    const float* emission    = (const float*)d_in[0];
    const int*   target      = (const int*)  d_in[1];
    const float* mask        = (const float*)d_in[2];
    const float* start_trans = (const float*)d_in[3];
    const float* trans       = (const float*)d_in[4];
    const float* end_trans   = (const float*)d_in[5];
    float* out = (float*)d_out;

    crf_main_kernel<<<KSEG * BB, 32>>>(emission, target, mask, start_trans,
                                       trans, end_trans, out);
}

// round 16
// speedup vs baseline: 1.1352x; 1.1352x over previous
#include <cuda_runtime.h>
#include <cuda_bf16.h>

#define BB 512
#define TT 512
#define LL 64
#define KSEG 8
#define WBURN 8

__device__ float g_res[BB];
__device__ float g_R[BB * KSEG];
__device__ float g_path[BB];
__device__ unsigned int g_cnt[BB];
__device__ unsigned int g_done = 0;

static __device__ __forceinline__ __nv_bfloat162 asbf2(unsigned int u) {
    return *reinterpret_cast<__nv_bfloat162*>(&u);
}
static __device__ __forceinline__ float bflo(__nv_bfloat162 v) {
    unsigned int u = *reinterpret_cast<unsigned int*>(&v);
    return __uint_as_float(u << 16);
}
static __device__ __forceinline__ float bfhi(__nv_bfloat162 v) {
    unsigned int u = *reinterpret_cast<unsigned int*>(&v);
    return __uint_as_float(u & 0xFFFF0000u);
}

__global__ void __launch_bounds__(32) crf_main_kernel(
    const float* __restrict__ emission,   // [B,T,L]
    const int*   __restrict__ target,     // [B,T]
    const float* __restrict__ mask,       // [B,T]
    const float* __restrict__ start_trans,// [L]
    const float* __restrict__ trans,      // [L,L]
    const float* __restrict__ end_trans,  // [L]
    float* __restrict__ out)
{
    __shared__ __align__(16) unsigned int sm_p[2][32]; // packed bf16x2 V
    __shared__ float sm_v0[2];

    const int lane = threadIdx.x;
    const int b    = blockIdx.x & (BB - 1);
    const int s    = blockIdx.x >> 9;            // segment 0..KSEG-1

    const float*  emb  = emission + (size_t)b * TT * LL;
    const float2* emb2 = (const float2*)emb;     // idx: t*32 + lane
    const float*  mrow = mask + (size_t)b * TT;

    // effective length Lb (binary prefix mask)
    float msum = 0.0f;
    for (int t = lane; t < TT; t += 32) msum += mrow[t];
    #pragma unroll
    for (int o = 16; o; o >>= 1) msum += __shfl_xor_sync(~0u, msum, o);
    const int Lb = (int)(msum + 0.5f);

    const int c0 = (s * (Lb - 1)) / KSEG;        // segment start point
    const int c1 = ((s + 1) * (Lb - 1)) / KSEG;  // segment end point
    int t0 = (s == 0) ? 0 : (c0 - WBURN);
    if (t0 < 0) t0 = 0;

    // E columns 2l, 2l+1, packed over i-pairs
    __nv_bfloat162 EpA[32], EpB[32];
    #pragma unroll
    for (int k = 0; k < 32; k++) {
        const float2 r0 = ((const float2*)trans)[(2 * k)     * 32 + lane];
        const float2 r1 = ((const float2*)trans)[(2 * k + 1) * 32 + lane];
        EpA[k] = __floats2bfloat162_rn(__expf(r0.x), __expf(r1.x));
        EpB[k] = __floats2bfloat162_rn(__expf(r0.y), __expf(r1.y));
    }

    // path score (segment-0 CTA only; exact fp32, general masked form)
    float pacc = 0.0f;
    if (s == 0) {
        const int* tgt = target + (size_t)b * TT;
        for (int t = 1 + lane; t < TT; t += 32) {
            const int   tp = tgt[t - 1];
            const int   tc = tgt[t];
            const float m  = mrow[t];
            const float nm = (t + 1 < TT) ? mrow[t + 1] : 0.0f;
            const float e  = (m > nm) ? 1.0f : 0.0f;
            pacc += m * (trans[tp * LL + tc] + emb[(size_t)t * LL + tc])
                  + e * end_trans[tc];
        }
        if (lane == 0) {
            const int tg0 = tgt[0];
            pacc += start_trans[tg0] + emb[tg0];
        }
        #pragma unroll
        for (int o = 16; o; o >>= 1) pacc += __shfl_xor_sync(~0u, pacc, o);
    }

    // ---- init at t0 ----
    const float2 em_t0 = emb2[(size_t)t0 * 32 + lane];
    float iA, iB;
    if (s == 0) {
        const float2 st2 = ((const float2*)start_trans)[lane];
        iA = st2.x + em_t0.x;
        iB = st2.y + em_t0.y;
    } else {
        iA = em_t0.x;
        iB = em_t0.y;
    }
    const float C0shift = __shfl_sync(~0u, iA, 0);
    float VA = __expf(iA - C0shift);
    float VB = __expf(iB - C0shift);
    {
        const __nv_bfloat162 pv = __floats2bfloat162_rn(VA, VB);
        sm_p[t0 & 1][lane] = *reinterpret_cast<const unsigned int*>(&pv);
        if (lane == 0) sm_v0[t0 & 1] = VA;
    }

    float C = 0.0f, prod = 1.0f, Sstart = 0.0f;
    if (c0 == t0) {                              // s==0 (or degenerate)
        float sum = VA + VB;
        #pragma unroll
        for (int o = 16; o; o >>= 1) sum += __shfl_xor_sync(~0u, sum, o);
        Sstart = __logf(sum);
    }

    // emission pipeline
    int i1 = t0 + 1; if (i1 > TT - 1) i1 = TT - 1;
    int i2 = t0 + 2; if (i2 > TT - 1) i2 = TT - 1;
    float2 em1 = emb2[(size_t)i1 * 32 + lane];
    float2 em2 = emb2[(size_t)i2 * 32 + lane];
    float XcA = __expf(em1.x), XcB = __expf(em1.y);
    __syncwarp();

    for (int t = t0 + 1; t <= c1; t++) {
        const int pb = (t - 1) & 1, cb = t & 1;
        const float u0 = sm_v0[pb];
        float w;
        asm("rcp.approx.f32 %0, %1;" : "=f"(w) : "f"(u0));
        const float XnA = __expf(em2.x);
        const float XnB = __expf(em2.y);
        if (t + 2 < TT) em2 = emb2[(size_t)(t + 2) * 32 + lane];

        // dot over i for both labels: 64 HFMA2
        const uint4* q = (const uint4*)sm_p[pb];
        const __nv_bfloat162 z2 = __float2bfloat162_rn(0.0f);
        __nv_bfloat162 a0 = z2, a1 = z2, a2 = z2, a3 = z2;
        __nv_bfloat162 c0v = z2, c1v = z2, c2v = z2, c3v = z2;
        #pragma unroll
        for (int k = 0; k < 8; k++) {
            const uint4 uu = q[k];
            const __nv_bfloat162 q0 = asbf2(uu.x);
            const __nv_bfloat162 q1 = asbf2(uu.y);
            const __nv_bfloat162 q2 = asbf2(uu.z);
            const __nv_bfloat162 q3 = asbf2(uu.w);
            a0  = __hfma2(q0, EpA[4 * k + 0], a0);
            c0v = __hfma2(q0, EpB[4 * k + 0], c0v);
            a1  = __hfma2(q1, EpA[4 * k + 1], a1);
            c1v = __hfma2(q1, EpB[4 * k + 1], c1v);
            a2  = __hfma2(q2, EpA[4 * k + 2], a2);
            c2v = __hfma2(q2, EpB[4 * k + 2], c2v);
            a3  = __hfma2(q3, EpA[4 * k + 3], a3);
            c3v = __hfma2(q3, EpB[4 * k + 3], c3v);
        }
        const __nv_bfloat162 tA = __hadd2(__hadd2(a0, a1), __hadd2(a2, a3));
        const __nv_bfloat162 tB = __hadd2(__hadd2(c0v, c1v), __hadd2(c2v, c3v));
        const float dotA = bflo(tA) + bfhi(tA);
        const float dotB = bflo(tB) + bfhi(tB);

        VA = dotA * (XcA * w);
        VB = dotB * (XcB * w);
        prod *= u0;
        if ((t & 3) == 0) { C += __logf(prod); prod = 1.0f; }

        if (t == c0) {                           // end of burn-in: reset stats
            C = 0.0f; prod = 1.0f;
            float sum = VA + VB;
            #pragma unroll
            for (int o = 16; o; o >>= 1) sum += __shfl_xor_sync(~0u, sum, o);
            Sstart = __logf(sum);
        }

        const __nv_bfloat162 pv = __floats2bfloat162_rn(VA, VB);
        sm_p[cb][lane] = *reinterpret_cast<const unsigned int*>(&pv);
        if (lane == 0) sm_v0[cb] = VA;
        XcA = XnA; XcB = XnB;
        __syncwarp();
    }
    C += __logf(prod);

    if (s == KSEG - 1) {                         // fold end_trans at t=Lb-1
        const float2 et2 = ((const float2*)end_trans)[lane];
        VA *= __expf(et2.x);
        VB *= __expf(et2.y);
    }
    float sum = VA + VB;
    #pragma unroll
    for (int o = 16; o; o >>= 1) sum += __shfl_xor_sync(~0u, sum, o);
    float Rs = C + __logf(sum) - Sstart;
    if (s == 0) Rs += Sstart + C0shift;          // + log F_0

    // ---------------- per-batch combine, then global mean ----------------
    if (lane == 0) {
        g_R[b * KSEG + s] = Rs;
        if (s == 0) g_path[b] = pacc;
    }
    __threadfence();
    unsigned int tk = 0;
    if (lane == 0) tk = atomicAdd(&g_cnt[b], 1u);
    tk = __shfl_sync(~0u, tk, 0);
    if (tk == KSEG - 1) {                        // last segment for batch b
        __threadfence();
        unsigned int td = 0;
        if (lane == 0) {
            float z = 0.0f;
            #pragma unroll
            for (int k = 0; k < KSEG; k++) z += g_R[b * KSEG + k];
            g_res[b] = z - g_path[b];
            g_cnt[b] = 0;                        // reset for graph replay
            __threadfence();
            td = atomicAdd(&g_done, 1u);         // BB-1 for the last batch
        }
        td = __shfl_sync(~0u, td, 0);
        if (td == BB - 1) {
            __threadfence();                     // acquire all g_res
            float acc = 0.0f;
            #pragma unroll
            for (int k = 0; k < BB / 32; k++) acc += g_res[lane + k * 32];
            #pragma unroll
            for (int o = 16; o; o >>= 1) acc += __shfl_xor_sync(~0u, acc, o);
            if (lane == 0) {
                out[0] = acc * (1.0f / BB);
                g_done = 0;                      // reset for graph replay
            }
        }
    }
}

extern "C" void kernel_launch(void* const* d_in, const int* in_sizes, int n_in,
                              void* d_out, int out_size) {
    const float* emission    = (const float*)d_in[0];
    const int*   target      = (const int*)  d_in[1];
    const float* mask        = (const float*)d_in[2];
    const float* start_trans = (const float*)d_in[3];
    const float* trans       = (const float*)d_in[4];
    const float* end_trans   = (const float*)d_in[5];
    float* out = (float*)d_out;

    crf_main_kernel<<<KSEG * BB, 32>>>(emission, target, mask, start_trans,
                                       trans, end_trans, out);
}